// round 15
// baseline (speedup 1.0000x reference)
#include <cuda_runtime.h>
#include <cuda_fp16.h>
#include <cstdint>
#include <math.h>

// ======================= problem dims =======================
#define UU      356
#define GATES   1424
#define BSZ     8192
#define TS      7
#define FENC    69
#define FDEC    45
#define H1      1024
#define OUTN    168

#define HPAD    384
#define XPAD    128
#define MPAD    64
#define DPAD    2496
#define GNPAD   1536
#define ONPAD   256
#define BT      (BSZ*TS)
#define NSPLIT  8
#define HB      (BSZ/NSPLIT)      // 1024
#define BTH     (BT/NSPLIT)       // 7168

// ======================= scratch (device globals) =======================
__device__ __half g_x[(size_t)BT*XPAD];
__device__ __half g_m[(size_t)BT*MPAD];
__device__ float  g_xw [(size_t)BT*GATES];
__device__ float  g_xw2[(size_t)BT*GATES];
__device__ float  g_z [(size_t)BSZ*GATES];
__device__ float  g_c [(size_t)BSZ*UU];
__device__ __half g_h [(size_t)BSZ*HPAD];
__device__ __half g_d [(size_t)BSZ*DPAD];
__device__ __half g_t1[(size_t)BSZ*H1];
__device__ __half g_t2[(size_t)BSZ*H1];
// weights: transposed, padded [Npad, Kpad], fp16 hi/lo (lo used only by recurrence)
__device__ __half w_encW_hi[(size_t)GNPAD*XPAD], w_encW_lo[(size_t)GNPAD*XPAD];
__device__ __half w_decW_hi[(size_t)GNPAD*MPAD], w_decW_lo[(size_t)GNPAD*MPAD];
__device__ __half w_encU_hi[(size_t)GNPAD*HPAD], w_encU_lo[(size_t)GNPAD*HPAD];
__device__ __half w_decU_hi[(size_t)GNPAD*HPAD], w_decU_lo[(size_t)GNPAD*HPAD];
__device__ __half w_map_hi[(size_t)H1*DPAD],     w_map_lo[(size_t)H1*DPAD];
__device__ __half w_1_hi[(size_t)H1*H1], w_1_lo[(size_t)H1*H1];
__device__ __half w_2_hi[(size_t)H1*H1], w_2_lo[(size_t)H1*H1];
__device__ __half w_3_hi[(size_t)H1*H1], w_3_lo[(size_t)H1*H1];
__device__ __half w_out_hi[(size_t)ONPAD*H1],    w_out_lo[(size_t)ONPAD*H1];

// ======================= streams/events (process-start init, checkpoint-safe)
struct StreamPack {
    cudaStream_t st[NSPLIT];
    cudaEvent_t  ev_fork, ev_join, ev_p[NSPLIT];
    StreamPack() {
        for (int k = 0; k < NSPLIT; k++) {
            cudaStreamCreateWithFlags(&st[k], cudaStreamNonBlocking);
            cudaEventCreateWithFlags(&ev_p[k], cudaEventDisableTiming);
        }
        cudaEventCreateWithFlags(&ev_fork, cudaEventDisableTiming);
        cudaEventCreateWithFlags(&ev_join, cudaEventDisableTiming);
    }
};
static StreamPack g_sp;

// ======================= PTX helpers (sm_80-era) =======================
__device__ __forceinline__ uint32_t smem_u32(const void* p) {
    uint32_t a;
    asm("{ .reg .u64 t; cvta.to.shared.u64 t, %1; cvt.u32.u64 %0, t; }" : "=r"(a) : "l"(p));
    return a;
}
#define CP_ASYNC16(dst, src) \
    asm volatile("cp.async.cg.shared.global [%0], [%1], 16;" :: "r"(dst), "l"(src))
#define CP_COMMIT()  asm volatile("cp.async.commit_group;" ::: "memory")
#define CP_WAIT1()   asm volatile("cp.async.wait_group 1;" ::: "memory")
#define LDSM4(r0,r1,r2,r3,addr) \
    asm volatile("ldmatrix.sync.aligned.m8n8.x4.shared.b16 {%0,%1,%2,%3}, [%4];" \
        : "=r"(r0),"=r"(r1),"=r"(r2),"=r"(r3) : "r"(addr))

__device__ __forceinline__ void mma16816(float* d, const uint32_t* a, const uint32_t* b) {
    asm volatile("mma.sync.aligned.m16n8k16.row.col.f32.f16.f16.f32 "
        "{%0,%1,%2,%3}, {%4,%5,%6,%7}, {%8,%9}, {%0,%1,%2,%3};"
        : "+f"(d[0]), "+f"(d[1]), "+f"(d[2]), "+f"(d[3])
        : "r"(a[0]), "r"(a[1]), "r"(a[2]), "r"(a[3]), "r"(b[0]), "r"(b[1]));
}

// fast transcendentals (MUFU-based)
__device__ __forceinline__ float fsig(float x) {
    return __fdividef(1.f, 1.f + __expf(-x));
}
__device__ __forceinline__ float ftanh(float x) {
    return __fmaf_rn(2.f, fsig(2.f * x), -1.f);
}

// ======================= HMMA GEMM =======================
// C[M,N] = act( A @ B^T (+Ci) (+bias) )
// A:[M,Kpad] fp16; B:[Npad,Kpad] fp16 (hi [+lo if DUAL]).
// CTA tile 128x128, 4 warps (2 M x 2 N), warp tile 64x64, BK=32,
// 3-stage cp.async. 90KB smem -> 2 CTAs/SM.
#define ROWB    80
#define A_TILEB (128*ROWB)
#define B_TILEB (128*ROWB)
#define STAGE   (A_TILEB + 2*B_TILEB)      // 30720 (lo slot unused if !DUAL)
#define NSTAGE  3
#define SMEM_BYTES (NSTAGE*STAGE)          // 92160

template<int ACT, bool BIAS, bool CINIT, bool WF32, bool WH, bool DUAL>
__global__ __launch_bounds__(128, 2)
void mma_gemm(int M, int N, int Kpad,
              const __half* __restrict__ A,
              const __half* __restrict__ Bhi, const __half* __restrict__ Blo,
              const float* __restrict__ bias,
              const float* __restrict__ Ci, int ldci,
              float* __restrict__ Cf, int ldc,
              __half* __restrict__ Ch, int ldcs)
{
    extern __shared__ char smem[];
    const uint32_t sbase = smem_u32(smem);
    const int tid  = threadIdx.x;
    const int lane = tid & 31;
    const int wid  = tid >> 5;
    const int warp_m = wid & 1;
    const int warp_n = wid >> 1;
    const int bm = blockIdx.y * 128;
    const int bn = blockIdx.x * 128;

    const int ld = Kpad * 2;
    const char* gA   = (const char*)A   + (size_t)bm * ld;
    const char* gBhi = (const char*)Bhi + (size_t)bn * ld;
    const char* gBlo = (const char*)Blo + (size_t)bn * ld;

    const int rr  = tid >> 2;
    const int seg = (tid & 3) * 16;

    float acc[4][8][4];
    #pragma unroll
    for (int i = 0; i < 4; i++)
        #pragma unroll
        for (int j = 0; j < 8; j++)
            #pragma unroll
            for (int q = 0; q < 4; q++) acc[i][j][q] = 0.f;

    const int NC = Kpad >> 5;

    auto stage_load = [&](int c) {
        uint32_t s = sbase + (c % NSTAGE) * STAGE;
        int ko = c << 6;
        #pragma unroll
        for (int i = 0; i < 4; i++) {
            int r = rr + i * 32;
            CP_ASYNC16(s + r*ROWB + seg, gA + (size_t)r*ld + ko + seg);
        }
        #pragma unroll
        for (int i = 0; i < 4; i++) {
            int r = rr + i * 32;
            CP_ASYNC16(s + A_TILEB + r*ROWB + seg, gBhi + (size_t)r*ld + ko + seg);
            if (DUAL)
                CP_ASYNC16(s + A_TILEB + B_TILEB + r*ROWB + seg, gBlo + (size_t)r*ld + ko + seg);
        }
    };

    stage_load(0); CP_COMMIT();
    if (NC > 1) { stage_load(1); }
    CP_COMMIT();

    const uint32_t aoff = (uint32_t)((warp_m*64 + (lane & 15)) * ROWB + (lane >> 4) * 16);
    const uint32_t boff = (uint32_t)((warp_n*64 + (lane >> 4)*8 + (lane & 7)) * ROWB
                                     + ((lane >> 3) & 1) * 16);

    for (int c = 0; c < NC; c++) {
        CP_WAIT1();
        __syncthreads();
        if (c + 2 < NC) stage_load(c + 2);
        CP_COMMIT();

        const uint32_t sb  = sbase + (c % NSTAGE) * STAGE;
        const uint32_t sA  = sb;
        const uint32_t sB0 = sb + A_TILEB;
        const uint32_t sB1 = sB0 + B_TILEB;

        #pragma unroll
        for (int kk = 0; kk < 2; kk++) {
            const uint32_t kb = kk * 32;
            uint32_t a[4][4], bhi[4][4], blo[4][4];
            #pragma unroll
            for (int mi = 0; mi < 4; mi++) {
                uint32_t ad = sA + aoff + mi * (16 * ROWB) + kb;
                LDSM4(a[mi][0], a[mi][1], a[mi][2], a[mi][3], ad);
            }
            #pragma unroll
            for (int g = 0; g < 4; g++) {
                uint32_t b = boff + g * (16 * ROWB) + kb;
                LDSM4(bhi[g][0], bhi[g][1], bhi[g][2], bhi[g][3], sB0 + b);
                if (DUAL) {
                    LDSM4(blo[g][0], blo[g][1], blo[g][2], blo[g][3], sB1 + b);
                }
            }
            #pragma unroll
            for (int mi = 0; mi < 4; mi++)
                #pragma unroll
                for (int nj = 0; nj < 8; nj++) {
                    const uint32_t* bh = &bhi[nj >> 1][(nj & 1) * 2];
                    mma16816(acc[mi][nj], a[mi], bh);
                    if (DUAL) {
                        const uint32_t* bl = &blo[nj >> 1][(nj & 1) * 2];
                        mma16816(acc[mi][nj], a[mi], bl);
                    }
                }
        }
        __syncthreads();
    }

    // ---- epilogue ----
    const int tr = lane >> 2;
    const int tc = (lane & 3) * 2;
    const int row0 = bm + warp_m * 64;
    const int col0 = bn + warp_n * 64;
    #pragma unroll
    for (int mi = 0; mi < 4; mi++)
        #pragma unroll
        for (int nj = 0; nj < 8; nj++) {
            int gc = col0 + nj * 8 + tc;
            if (gc >= N) continue;
            float b0 = 0.f, b1 = 0.f;
            if (BIAS) { b0 = bias[gc]; b1 = bias[gc + 1]; }
            #pragma unroll
            for (int hh = 0; hh < 2; hh++) {
                int gr = row0 + mi * 16 + hh * 8 + tr;
                float v0 = acc[mi][nj][hh * 2 + 0];
                float v1 = acc[mi][nj][hh * 2 + 1];
                if (CINIT) {
                    const float* ci = Ci + (size_t)gr * ldci + gc;
                    v0 += ci[0]; v1 += ci[1];
                }
                if (BIAS) { v0 += b0; v1 += b1; }
                if (ACT == 1) { v0 = fmaxf(v0, 0.f); v1 = fmaxf(v1, 0.f); }
                else if (ACT == 2) { v0 = ftanh(v0); v1 = ftanh(v1); }
                if (WF32) {
                    float2* p = (float2*)(Cf + (size_t)gr * ldc + gc);
                    *p = make_float2(v0, v1);
                }
                if (WH) {
                    *(__half2*)(Ch + (size_t)gr * ldcs + gc) =
                        __floats2half2_rn(v0, v1);
                }
            }
        }
}

// ======================= prep kernels =======================
__global__ void prep_weight(const float* __restrict__ W, int K, int N, int Kpad, int total,
                            __half* __restrict__ Whi, __half* __restrict__ Wlo)
{
    int idx = blockIdx.x * blockDim.x + threadIdx.x;
    if (idx >= total) return;
    int n = idx / Kpad, k = idx - n * Kpad;
    float v = (k < K && n < N) ? W[(size_t)k * N + n] : 0.f;
    __half hi = __float2half_rn(v);
    Whi[idx] = hi;
    Wlo[idx] = __float2half_rn(v - __half2float(hi));
}

__global__ void prep_act(const float* __restrict__ X, int total, int K, int Kpad,
                         __half* __restrict__ A)
{
    int idx = blockIdx.x * blockDim.x + threadIdx.x;
    if (idx >= total) return;
    int r = idx / Kpad, k = idx - r * Kpad;
    A[idx] = __float2half_rn((k < K) ? X[(size_t)r * K + k] : 0.f);
}

// ======================= LSTM gates (2 units/thread, fast math) ==========
__global__ void lstm_gates(int Mrows,
                           const float* __restrict__ z, float* __restrict__ c,
                           __half* __restrict__ h, __half* __restrict__ d, int t)
{
    int idx = blockIdx.x * blockDim.x + threadIdx.x;
    const int TOT = Mrows * (UU / 2);
    if (idx >= TOT) return;
    int b = idx / (UU / 2);
    int j = (idx - b * (UU / 2)) * 2;
    const float* zr = z + (size_t)b * GATES;
    float2 zi = *(const float2*)(zr + j);
    float2 zf = *(const float2*)(zr + UU + j);
    float2 zg = *(const float2*)(zr + 2 * UU + j);
    float2 zo = *(const float2*)(zr + 3 * UU + j);
    float2 cv = *(const float2*)(c + (size_t)b * UU + j);

    float cn0 = fsig(zf.x) * cv.x + fsig(zi.x) * ftanh(zg.x);
    float cn1 = fsig(zf.y) * cv.y + fsig(zi.y) * ftanh(zg.y);
    *(float2*)(c + (size_t)b * UU + j) = make_float2(cn0, cn1);
    __half2 hv = __floats2half2_rn(fsig(zo.x) * ftanh(cn0),
                                   fsig(zo.y) * ftanh(cn1));
    *(__half2*)(h + (size_t)b * HPAD + j) = hv;
    if (d) *(__half2*)(d + (size_t)b * DPAD + t * UU + j) = hv;
}

// ======================= host side =======================
template<int ACT, bool BIAS, bool CINIT, bool WF32, bool WH, bool DUAL>
static inline void launch_mma(cudaStream_t s, int M, int N, int Kpad,
                              const __half* A, const __half* Bhi, const __half* Blo,
                              const float* bias, const float* Ci, int ldci,
                              float* Cf, int ldc, __half* Ch, int ldcs)
{
    dim3 grid((N + 127) / 128, M / 128);
    mma_gemm<ACT, BIAS, CINIT, WF32, WH, DUAL><<<grid, 128, SMEM_BYTES, s>>>(
        M, N, Kpad, A, Bhi, Blo, bias, Ci, ldci, Cf, ldc, Ch, ldcs);
}

static inline void set_attrs() {
    cudaFuncSetAttribute(mma_gemm<0, true,  false, true,  false, false>, cudaFuncAttributeMaxDynamicSharedMemorySize, SMEM_BYTES);
    cudaFuncSetAttribute(mma_gemm<0, false, true,  true,  false, true >, cudaFuncAttributeMaxDynamicSharedMemorySize, SMEM_BYTES);
    cudaFuncSetAttribute(mma_gemm<1, true,  false, false, true,  false>, cudaFuncAttributeMaxDynamicSharedMemorySize, SMEM_BYTES);
    cudaFuncSetAttribute(mma_gemm<2, true,  false, false, true,  false>, cudaFuncAttributeMaxDynamicSharedMemorySize, SMEM_BYTES);
}

extern "C" void kernel_launch(void* const* d_in, const int* /*in_sizes*/, int /*n_in*/,
                              void* d_out, int /*out_size*/)
{
    const float* x     = (const float*)d_in[0];
    const float* m     = (const float*)d_in[1];
    const float* enc_W = (const float*)d_in[2];
    const float* enc_U = (const float*)d_in[3];
    const float* enc_b = (const float*)d_in[4];
    const float* dec_W = (const float*)d_in[5];
    const float* dec_U = (const float*)d_in[6];
    const float* dec_b = (const float*)d_in[7];
    const float* W_map = (const float*)d_in[8];
    const float* b_map = (const float*)d_in[9];
    const float* W1    = (const float*)d_in[10];
    const float* b1    = (const float*)d_in[11];
    const float* W2    = (const float*)d_in[12];
    const float* b2    = (const float*)d_in[13];
    const float* W3    = (const float*)d_in[14];
    const float* b3    = (const float*)d_in[15];
    const float* W_out = (const float*)d_in[16];
    const float* b_out = (const float*)d_in[17];
    float* out = (float*)d_out;

    set_attrs();

    __half *xa,*ma,*h,*d,*t1,*t2;
    __half *eWh,*eWl,*dWh,*dWl,*eUh,*eUl,*dUh,*dUl,*wmh,*wml,*w1h,*w1l,*w2h,*w2l,*w3h,*w3l,*woh,*wol;
    float *xw,*xw2,*z,*c;
    cudaGetSymbolAddress((void**)&xa, g_x);   cudaGetSymbolAddress((void**)&ma, g_m);
    cudaGetSymbolAddress((void**)&h,  g_h);   cudaGetSymbolAddress((void**)&d,  g_d);
    cudaGetSymbolAddress((void**)&t1, g_t1);  cudaGetSymbolAddress((void**)&t2, g_t2);
    cudaGetSymbolAddress((void**)&eWh, w_encW_hi); cudaGetSymbolAddress((void**)&eWl, w_encW_lo);
    cudaGetSymbolAddress((void**)&dWh, w_decW_hi); cudaGetSymbolAddress((void**)&dWl, w_decW_lo);
    cudaGetSymbolAddress((void**)&eUh, w_encU_hi); cudaGetSymbolAddress((void**)&eUl, w_encU_lo);
    cudaGetSymbolAddress((void**)&dUh, w_decU_hi); cudaGetSymbolAddress((void**)&dUl, w_decU_lo);
    cudaGetSymbolAddress((void**)&wmh, w_map_hi);  cudaGetSymbolAddress((void**)&wml, w_map_lo);
    cudaGetSymbolAddress((void**)&w1h, w_1_hi);    cudaGetSymbolAddress((void**)&w1l, w_1_lo);
    cudaGetSymbolAddress((void**)&w2h, w_2_hi);    cudaGetSymbolAddress((void**)&w2l, w_2_lo);
    cudaGetSymbolAddress((void**)&w3h, w_3_hi);    cudaGetSymbolAddress((void**)&w3l, w_3_lo);
    cudaGetSymbolAddress((void**)&woh, w_out_hi);  cudaGetSymbolAddress((void**)&wol, w_out_lo);
    cudaGetSymbolAddress((void**)&xw,  g_xw);
    cudaGetSymbolAddress((void**)&xw2, g_xw2);
    cudaGetSymbolAddress((void**)&z,   g_z);
    cudaGetSymbolAddress((void**)&c,   g_c);

    // ---- fork ----
    cudaEventRecord(g_sp.ev_fork, 0);
    for (int k = 0; k < NSPLIT; k++)
        cudaStreamWaitEvent(g_sp.st[k], g_sp.ev_fork, 0);

    auto pw = [](cudaStream_t s, const float* W, int K, int N, int Kpad, int Npad,
                 __half* hi, __half* lo) {
        int total = Npad * Kpad;
        prep_weight<<<(total + 255) / 256, 256, 0, s>>>(W, K, N, Kpad, total, hi, lo);
    };

    // distributed weight preps (LSTM weights first on st0-3 for fast chain start)
    pw(g_sp.st[0], enc_W, FENC, GATES, XPAD, GNPAD, eWh, eWl);
    pw(g_sp.st[1], dec_W, FDEC, GATES, MPAD, GNPAD, dWh, dWl);
    pw(g_sp.st[2], enc_U, UU, GATES, HPAD, GNPAD, eUh, eUl);
    pw(g_sp.st[3], dec_U, UU, GATES, HPAD, GNPAD, dUh, dUl);
    pw(g_sp.st[4], W1, H1, H1, H1, H1, w1h, w1l);
    pw(g_sp.st[5], W2, H1, H1, H1, H1, w2h, w2l);
    pw(g_sp.st[6], W3, H1, H1, H1, H1, w3h, w3l);
    pw(g_sp.st[7], W_map, TS*UU, H1, DPAD, H1, wmh, wml);
    pw(g_sp.st[4], W_out, H1, OUTN, H1, ONPAD, woh, wol);

    // all-to-all barrier on weight preps
    for (int k = 0; k < NSPLIT; k++)
        cudaEventRecord(g_sp.ev_p[k], g_sp.st[k]);
    for (int k = 0; k < NSPLIT; k++)
        for (int j = 0; j < NSPLIT; j++)
            if (j != k) cudaStreamWaitEvent(g_sp.st[k], g_sp.ev_p[j], 0);

    const int gate_grid = (HB * (UU / 2) + 255) / 256;

    for (int k = 0; k < NSPLIT; k++) {
        cudaStream_t s = g_sp.st[k];
        const __half* xa_k = xa + (size_t)k * BTH * XPAD;
        const __half* ma_k = ma + (size_t)k * BTH * MPAD;
        float*  xw_k  = xw  + (size_t)k * BTH * GATES;
        float*  xw2_k = xw2 + (size_t)k * BTH * GATES;
        float*  z_k  = z  + (size_t)k * HB * GATES;
        float*  c_k  = c  + (size_t)k * HB * UU;
        __half* h_k  = h  + (size_t)k * HB * HPAD;
        __half* d_k  = d  + (size_t)k * HB * DPAD;
        __half* t1_k = t1 + (size_t)k * HB * H1;
        __half* t2_k = t2 + (size_t)k * HB * H1;
        float*  out_k = out + (size_t)k * HB * OUTN;

        // slice-local prep
        cudaMemsetAsync(c_k, 0, (size_t)HB * UU * sizeof(float), s);
        cudaMemsetAsync(h_k, 0, (size_t)HB * HPAD * sizeof(__half), s);
        cudaMemsetAsync(d_k, 0, (size_t)HB * DPAD * sizeof(__half), s);
        {
            int tot = BTH * XPAD;
            prep_act<<<(tot + 255) / 256, 256, 0, s>>>(
                x + (size_t)k * BTH * FENC, tot, FENC, XPAD, (__half*)xa_k);
            tot = BTH * MPAD;
            prep_act<<<(tot + 255) / 256, 256, 0, s>>>(
                m + (size_t)k * BTH * FDEC, tot, FDEC, MPAD, (__half*)ma_k);
        }

        // input projections (single-pass weights)
        launch_mma<0, true, false, true, false, false>(s, BTH, GATES, XPAD, xa_k, eWh, eWl,
                                                       enc_b, nullptr, 0, xw_k, GATES, nullptr, 0);
        launch_mma<0, true, false, true, false, false>(s, BTH, GATES, MPAD, ma_k, dWh, dWl,
                                                       dec_b, nullptr, 0, xw2_k, GATES, nullptr, 0);

        // encoder recurrence (dual-pass weights)
        for (int t = 0; t < TS; t++) {
            launch_mma<0, false, true, true, false, true>(s, HB, GATES, HPAD, h_k, eUh, eUl,
                                                          nullptr, xw_k + (size_t)t * GATES, TS * GATES,
                                                          z_k, GATES, nullptr, 0);
            lstm_gates<<<gate_grid, 256, 0, s>>>(HB, z_k, c_k, h_k, nullptr, 0);
        }

        // decoder recurrence
        for (int t = 0; t < TS; t++) {
            launch_mma<0, false, true, true, false, true>(s, HB, GATES, HPAD, h_k, dUh, dUl,
                                                          nullptr, xw2_k + (size_t)t * GATES, TS * GATES,
                                                          z_k, GATES, nullptr, 0);
            lstm_gates<<<gate_grid, 256, 0, s>>>(HB, z_k, c_k, h_k, d_k, t);
        }

        // MLP head (single-pass weights)
        launch_mma<1, true, false, false, true, false>(s, HB, H1, DPAD, d_k, wmh, wml,
                                                       b_map, nullptr, 0, nullptr, 0, t1_k, H1);
        launch_mma<2, true, false, false, true, false>(s, HB, H1, H1, t1_k, w1h, w1l,
                                                       b1, nullptr, 0, nullptr, 0, t2_k, H1);
        launch_mma<2, true, false, false, true, false>(s, HB, H1, H1, t2_k, w2h, w2l,
                                                       b2, nullptr, 0, nullptr, 0, t1_k, H1);
        launch_mma<2, true, false, false, true, false>(s, HB, H1, H1, t1_k, w3h, w3l,
                                                       b3, nullptr, 0, nullptr, 0, t2_k, H1);
        launch_mma<0, true, false, true, false, false>(s, HB, OUTN, H1, t2_k, woh, wol,
                                                       b_out, nullptr, 0, out_k, OUTN, nullptr, 0);
    }

    // ---- join ----
    for (int k = 0; k < NSPLIT; k++) {
        cudaEventRecord(g_sp.ev_join, g_sp.st[k]);
        cudaStreamWaitEvent(0, g_sp.ev_join, 0);
    }
}

// round 16
// speedup vs baseline: 1.0074x; 1.0074x over previous
#include <cuda_runtime.h>
#include <cuda_fp16.h>
#include <cstdint>
#include <math.h>

// ======================= problem dims =======================
#define UU      356
#define GATES   1424
#define BSZ     8192
#define TS      7
#define FENC    69
#define FDEC    45
#define H1      1024
#define OUTN    168

#define HPAD    384
#define XPAD    96
#define MPAD    64
#define DPAD    2496
#define GNPAD   1536
#define ONPAD   256
#define NLO     384               // lo-pass column limit (g-gate block, padded)
#define BT      (BSZ*TS)
#define NSPLIT  8
#define HB      (BSZ/NSPLIT)      // 1024
#define BTH     (BT/NSPLIT)       // 7168

// ======================= scratch (device globals) =======================
__device__ __half g_x[(size_t)BT*XPAD];
__device__ __half g_m[(size_t)BT*MPAD];
__device__ float  g_xw [(size_t)BT*GATES];        // gate order [g|i|f|o]
__device__ float  g_xw2[(size_t)BT*GATES];
__device__ float  g_z [(size_t)BSZ*GATES];
__device__ float  g_c [(size_t)BSZ*UU];
__device__ __half g_h [(size_t)BSZ*HPAD];
__device__ __half g_d [(size_t)BSZ*DPAD];
__device__ __half g_t1[(size_t)BSZ*H1];
__device__ __half g_t2[(size_t)BSZ*H1];
// weights: transposed, padded [Npad, Kpad], fp16 hi/lo.
// LSTM weights gate-permuted to [g|i|f|o]; lo used only for cols < NLO.
__device__ __half w_encW_hi[(size_t)GNPAD*XPAD], w_encW_lo[(size_t)GNPAD*XPAD];
__device__ __half w_decW_hi[(size_t)GNPAD*MPAD], w_decW_lo[(size_t)GNPAD*MPAD];
__device__ __half w_encU_hi[(size_t)GNPAD*HPAD], w_encU_lo[(size_t)GNPAD*HPAD];
__device__ __half w_decU_hi[(size_t)GNPAD*HPAD], w_decU_lo[(size_t)GNPAD*HPAD];
__device__ __half w_map_hi[(size_t)H1*DPAD],     w_map_lo[(size_t)H1*DPAD];
__device__ __half w_1_hi[(size_t)H1*H1], w_1_lo[(size_t)H1*H1];
__device__ __half w_2_hi[(size_t)H1*H1], w_2_lo[(size_t)H1*H1];
__device__ __half w_3_hi[(size_t)H1*H1], w_3_lo[(size_t)H1*H1];
__device__ __half w_out_hi[(size_t)ONPAD*H1],    w_out_lo[(size_t)ONPAD*H1];

// ======================= streams/events (process-start init, checkpoint-safe)
struct StreamPack {
    cudaStream_t st[NSPLIT];
    cudaEvent_t  ev_fork, ev_join, ev_p[NSPLIT];
    StreamPack() {
        for (int k = 0; k < NSPLIT; k++) {
            cudaStreamCreateWithFlags(&st[k], cudaStreamNonBlocking);
            cudaEventCreateWithFlags(&ev_p[k], cudaEventDisableTiming);
        }
        cudaEventCreateWithFlags(&ev_fork, cudaEventDisableTiming);
        cudaEventCreateWithFlags(&ev_join, cudaEventDisableTiming);
    }
};
static StreamPack g_sp;

// ======================= PTX helpers (sm_80-era) =======================
__device__ __forceinline__ uint32_t smem_u32(const void* p) {
    uint32_t a;
    asm("{ .reg .u64 t; cvta.to.shared.u64 t, %1; cvt.u32.u64 %0, t; }" : "=r"(a) : "l"(p));
    return a;
}
#define CP_ASYNC16(dst, src) \
    asm volatile("cp.async.cg.shared.global [%0], [%1], 16;" :: "r"(dst), "l"(src))
#define CP_COMMIT()  asm volatile("cp.async.commit_group;" ::: "memory")
#define CP_WAIT1()   asm volatile("cp.async.wait_group 1;" ::: "memory")
#define LDSM4(r0,r1,r2,r3,addr) \
    asm volatile("ldmatrix.sync.aligned.m8n8.x4.shared.b16 {%0,%1,%2,%3}, [%4];" \
        : "=r"(r0),"=r"(r1),"=r"(r2),"=r"(r3) : "r"(addr))

__device__ __forceinline__ void mma16816(float* d, const uint32_t* a, const uint32_t* b) {
    asm volatile("mma.sync.aligned.m16n8k16.row.col.f32.f16.f16.f32 "
        "{%0,%1,%2,%3}, {%4,%5,%6,%7}, {%8,%9}, {%0,%1,%2,%3};"
        : "+f"(d[0]), "+f"(d[1]), "+f"(d[2]), "+f"(d[3])
        : "r"(a[0]), "r"(a[1]), "r"(a[2]), "r"(a[3]), "r"(b[0]), "r"(b[1]));
}

// fast transcendentals (MUFU-based)
__device__ __forceinline__ float fsig(float x) {
    return __fdividef(1.f, 1.f + __expf(-x));
}
__device__ __forceinline__ float ftanh(float x) {
    return __fmaf_rn(2.f, fsig(2.f * x), -1.f);
}

// gate permutation [g|i|f|o] -> source column in original [i|f|g|o]
__device__ __forceinline__ int gate_src(int n) {
    return (n < UU) ? (2 * UU + n) : ((n < 3 * UU) ? (n - UU) : n);
}

// ======================= HMMA GEMM =======================
// C[M,N] = act( A @ B^T (+Ci) (+bias) )
// A:[M,Kpad] fp16; B:[Npad,Kpad] fp16 hi (+lo for columns < nlo if DUAL).
// CTA tile 128x128, 4 warps (2 M x 2 N), warp tile 64x64, BK=32,
// 3-stage cp.async, 2 CTAs/SM.
#define ROWB    80
#define A_TILEB (128*ROWB)
#define B_TILEB (128*ROWB)
#define STAGE   (A_TILEB + 2*B_TILEB)      // 30720
#define NSTAGE  3
#define SMEM_BYTES (NSTAGE*STAGE)          // 92160

template<int ACT, bool BIAS, bool CINIT, bool WF32, bool WH, bool DUAL, bool PERMB>
__global__ __launch_bounds__(128, 2)
void mma_gemm(int M, int N, int Kpad, int nlo,
              const __half* __restrict__ A,
              const __half* __restrict__ Bhi, const __half* __restrict__ Blo,
              const float* __restrict__ bias,
              const float* __restrict__ Ci, int ldci,
              float* __restrict__ Cf, int ldc,
              __half* __restrict__ Ch, int ldcs)
{
    extern __shared__ char smem[];
    const uint32_t sbase = smem_u32(smem);
    const int tid  = threadIdx.x;
    const int lane = tid & 31;
    const int wid  = tid >> 5;
    const int warp_m = wid & 1;
    const int warp_n = wid >> 1;
    const int bm = blockIdx.y * 128;
    const int bn = blockIdx.x * 128;
    const bool do_lo = DUAL && (bn < nlo);

    const int ld = Kpad * 2;
    const char* gA   = (const char*)A   + (size_t)bm * ld;
    const char* gBhi = (const char*)Bhi + (size_t)bn * ld;
    const char* gBlo = (const char*)Blo + (size_t)bn * ld;

    const int rr  = tid >> 2;
    const int seg = (tid & 3) * 16;

    float acc[4][8][4];
    #pragma unroll
    for (int i = 0; i < 4; i++)
        #pragma unroll
        for (int j = 0; j < 8; j++)
            #pragma unroll
            for (int q = 0; q < 4; q++) acc[i][j][q] = 0.f;

    const int NC = Kpad >> 5;

    auto stage_load = [&](int c) {
        uint32_t s = sbase + (c % NSTAGE) * STAGE;
        int ko = c << 6;
        #pragma unroll
        for (int i = 0; i < 4; i++) {
            int r = rr + i * 32;
            CP_ASYNC16(s + r*ROWB + seg, gA + (size_t)r*ld + ko + seg);
        }
        #pragma unroll
        for (int i = 0; i < 4; i++) {
            int r = rr + i * 32;
            CP_ASYNC16(s + A_TILEB + r*ROWB + seg, gBhi + (size_t)r*ld + ko + seg);
            if (do_lo)
                CP_ASYNC16(s + A_TILEB + B_TILEB + r*ROWB + seg, gBlo + (size_t)r*ld + ko + seg);
        }
    };

    stage_load(0); CP_COMMIT();
    if (NC > 1) { stage_load(1); }
    CP_COMMIT();

    const uint32_t aoff = (uint32_t)((warp_m*64 + (lane & 15)) * ROWB + (lane >> 4) * 16);
    const uint32_t boff = (uint32_t)((warp_n*64 + (lane >> 4)*8 + (lane & 7)) * ROWB
                                     + ((lane >> 3) & 1) * 16);

    for (int c = 0; c < NC; c++) {
        CP_WAIT1();
        __syncthreads();
        if (c + 2 < NC) stage_load(c + 2);
        CP_COMMIT();

        const uint32_t sb  = sbase + (c % NSTAGE) * STAGE;
        const uint32_t sA  = sb;
        const uint32_t sB0 = sb + A_TILEB;
        const uint32_t sB1 = sB0 + B_TILEB;

        #pragma unroll
        for (int kk = 0; kk < 2; kk++) {
            const uint32_t kb = kk * 32;
            uint32_t a[4][4], bhi[4][4], blo[4][4];
            #pragma unroll
            for (int mi = 0; mi < 4; mi++) {
                uint32_t ad = sA + aoff + mi * (16 * ROWB) + kb;
                LDSM4(a[mi][0], a[mi][1], a[mi][2], a[mi][3], ad);
            }
            #pragma unroll
            for (int g = 0; g < 4; g++) {
                uint32_t b = boff + g * (16 * ROWB) + kb;
                LDSM4(bhi[g][0], bhi[g][1], bhi[g][2], bhi[g][3], sB0 + b);
                if (do_lo) {
                    LDSM4(blo[g][0], blo[g][1], blo[g][2], blo[g][3], sB1 + b);
                }
            }
            #pragma unroll
            for (int mi = 0; mi < 4; mi++)
                #pragma unroll
                for (int nj = 0; nj < 8; nj++) {
                    const uint32_t* bh = &bhi[nj >> 1][(nj & 1) * 2];
                    mma16816(acc[mi][nj], a[mi], bh);
                    if (do_lo) {
                        const uint32_t* bl = &blo[nj >> 1][(nj & 1) * 2];
                        mma16816(acc[mi][nj], a[mi], bl);
                    }
                }
        }
        __syncthreads();
    }

    // ---- epilogue ----
    const int tr = lane >> 2;
    const int tc = (lane & 3) * 2;
    const int row0 = bm + warp_m * 64;
    const int col0 = bn + warp_n * 64;
    #pragma unroll
    for (int mi = 0; mi < 4; mi++)
        #pragma unroll
        for (int nj = 0; nj < 8; nj++) {
            int gc = col0 + nj * 8 + tc;
            if (gc >= N) continue;
            float b0 = 0.f, b1 = 0.f;
            if (BIAS) {
                if (PERMB) { b0 = bias[gate_src(gc)]; b1 = bias[gate_src(gc + 1)]; }
                else       { b0 = bias[gc];           b1 = bias[gc + 1]; }
            }
            #pragma unroll
            for (int hh = 0; hh < 2; hh++) {
                int gr = row0 + mi * 16 + hh * 8 + tr;
                float v0 = acc[mi][nj][hh * 2 + 0];
                float v1 = acc[mi][nj][hh * 2 + 1];
                if (CINIT) {
                    const float* ci = Ci + (size_t)gr * ldci + gc;
                    v0 += ci[0]; v1 += ci[1];
                }
                if (BIAS) { v0 += b0; v1 += b1; }
                if (ACT == 1) { v0 = fmaxf(v0, 0.f); v1 = fmaxf(v1, 0.f); }
                else if (ACT == 2) { v0 = ftanh(v0); v1 = ftanh(v1); }
                if (WF32) {
                    float2* p = (float2*)(Cf + (size_t)gr * ldc + gc);
                    *p = make_float2(v0, v1);
                }
                if (WH) {
                    *(__half2*)(Ch + (size_t)gr * ldcs + gc) =
                        __floats2half2_rn(v0, v1);
                }
            }
        }
}

// ======================= prep kernels =======================
// perm: output column n <- original column gate_src(n) ([g|i|f|o] order)
__global__ void prep_weight(const float* __restrict__ W, int K, int N, int Kpad, int total,
                            int perm, __half* __restrict__ Whi, __half* __restrict__ Wlo)
{
    int idx = blockIdx.x * blockDim.x + threadIdx.x;
    if (idx >= total) return;
    int n = idx / Kpad, k = idx - n * Kpad;
    int nsrc = n;
    if (perm && n < GATES) nsrc = (n < UU) ? (2 * UU + n) : ((n < 3 * UU) ? (n - UU) : n);
    float v = (k < K && n < N) ? W[(size_t)k * N + nsrc] : 0.f;
    __half hi = __float2half_rn(v);
    Whi[idx] = hi;
    Wlo[idx] = __float2half_rn(v - __half2float(hi));
}

__global__ void prep_act(const float* __restrict__ X, int total, int K, int Kpad,
                         __half* __restrict__ A)
{
    int idx = blockIdx.x * blockDim.x + threadIdx.x;
    if (idx >= total) return;
    int r = idx / Kpad, k = idx - r * Kpad;
    A[idx] = __float2half_rn((k < K) ? X[(size_t)r * K + k] : 0.f);
}

// ======================= LSTM gates (permuted z layout [g|i|f|o]) ========
__global__ void lstm_gates(int Mrows,
                           const float* __restrict__ z, float* __restrict__ c,
                           __half* __restrict__ h, __half* __restrict__ d, int t)
{
    int idx = blockIdx.x * blockDim.x + threadIdx.x;
    const int TOT = Mrows * (UU / 2);
    if (idx >= TOT) return;
    int b = idx / (UU / 2);
    int j = (idx - b * (UU / 2)) * 2;
    const float* zr = z + (size_t)b * GATES;
    float2 zg = *(const float2*)(zr + j);
    float2 zi = *(const float2*)(zr + UU + j);
    float2 zf = *(const float2*)(zr + 2 * UU + j);
    float2 zo = *(const float2*)(zr + 3 * UU + j);
    float2 cv = *(const float2*)(c + (size_t)b * UU + j);

    float cn0 = fsig(zf.x) * cv.x + fsig(zi.x) * ftanh(zg.x);
    float cn1 = fsig(zf.y) * cv.y + fsig(zi.y) * ftanh(zg.y);
    *(float2*)(c + (size_t)b * UU + j) = make_float2(cn0, cn1);
    __half2 hv = __floats2half2_rn(fsig(zo.x) * ftanh(cn0),
                                   fsig(zo.y) * ftanh(cn1));
    *(__half2*)(h + (size_t)b * HPAD + j) = hv;
    if (d) *(__half2*)(d + (size_t)b * DPAD + t * UU + j) = hv;
}

// ======================= host side =======================
template<int ACT, bool BIAS, bool CINIT, bool WF32, bool WH, bool DUAL, bool PERMB = false>
static inline void launch_mma(cudaStream_t s, int M, int N, int Kpad, int nlo,
                              const __half* A, const __half* Bhi, const __half* Blo,
                              const float* bias, const float* Ci, int ldci,
                              float* Cf, int ldc, __half* Ch, int ldcs)
{
    dim3 grid((N + 127) / 128, M / 128);
    mma_gemm<ACT, BIAS, CINIT, WF32, WH, DUAL, PERMB><<<grid, 128, SMEM_BYTES, s>>>(
        M, N, Kpad, nlo, A, Bhi, Blo, bias, Ci, ldci, Cf, ldc, Ch, ldcs);
}

static inline void set_attrs() {
    cudaFuncSetAttribute(mma_gemm<0, true,  false, true,  false, false, true >, cudaFuncAttributeMaxDynamicSharedMemorySize, SMEM_BYTES);
    cudaFuncSetAttribute(mma_gemm<0, false, true,  true,  false, true,  false>, cudaFuncAttributeMaxDynamicSharedMemorySize, SMEM_BYTES);
    cudaFuncSetAttribute(mma_gemm<1, true,  false, false, true,  false, false>, cudaFuncAttributeMaxDynamicSharedMemorySize, SMEM_BYTES);
    cudaFuncSetAttribute(mma_gemm<2, true,  false, false, true,  false, false>, cudaFuncAttributeMaxDynamicSharedMemorySize, SMEM_BYTES);
    cudaFuncSetAttribute(mma_gemm<0, true,  false, true,  false, false, false>, cudaFuncAttributeMaxDynamicSharedMemorySize, SMEM_BYTES);
}

extern "C" void kernel_launch(void* const* d_in, const int* /*in_sizes*/, int /*n_in*/,
                              void* d_out, int /*out_size*/)
{
    const float* x     = (const float*)d_in[0];
    const float* m     = (const float*)d_in[1];
    const float* enc_W = (const float*)d_in[2];
    const float* enc_U = (const float*)d_in[3];
    const float* enc_b = (const float*)d_in[4];
    const float* dec_W = (const float*)d_in[5];
    const float* dec_U = (const float*)d_in[6];
    const float* dec_b = (const float*)d_in[7];
    const float* W_map = (const float*)d_in[8];
    const float* b_map = (const float*)d_in[9];
    const float* W1    = (const float*)d_in[10];
    const float* b1    = (const float*)d_in[11];
    const float* W2    = (const float*)d_in[12];
    const float* b2    = (const float*)d_in[13];
    const float* W3    = (const float*)d_in[14];
    const float* b3    = (const float*)d_in[15];
    const float* W_out = (const float*)d_in[16];
    const float* b_out = (const float*)d_in[17];
    float* out = (float*)d_out;

    set_attrs();

    __half *xa,*ma,*h,*d,*t1,*t2;
    __half *eWh,*eWl,*dWh,*dWl,*eUh,*eUl,*dUh,*dUl,*wmh,*wml,*w1h,*w1l,*w2h,*w2l,*w3h,*w3l,*woh,*wol;
    float *xw,*xw2,*z,*c;
    cudaGetSymbolAddress((void**)&xa, g_x);   cudaGetSymbolAddress((void**)&ma, g_m);
    cudaGetSymbolAddress((void**)&h,  g_h);   cudaGetSymbolAddress((void**)&d,  g_d);
    cudaGetSymbolAddress((void**)&t1, g_t1);  cudaGetSymbolAddress((void**)&t2, g_t2);
    cudaGetSymbolAddress((void**)&eWh, w_encW_hi); cudaGetSymbolAddress((void**)&eWl, w_encW_lo);
    cudaGetSymbolAddress((void**)&dWh, w_decW_hi); cudaGetSymbolAddress((void**)&dWl, w_decW_lo);
    cudaGetSymbolAddress((void**)&eUh, w_encU_hi); cudaGetSymbolAddress((void**)&eUl, w_encU_lo);
    cudaGetSymbolAddress((void**)&dUh, w_decU_hi); cudaGetSymbolAddress((void**)&dUl, w_decU_lo);
    cudaGetSymbolAddress((void**)&wmh, w_map_hi);  cudaGetSymbolAddress((void**)&wml, w_map_lo);
    cudaGetSymbolAddress((void**)&w1h, w_1_hi);    cudaGetSymbolAddress((void**)&w1l, w_1_lo);
    cudaGetSymbolAddress((void**)&w2h, w_2_hi);    cudaGetSymbolAddress((void**)&w2l, w_2_lo);
    cudaGetSymbolAddress((void**)&w3h, w_3_hi);    cudaGetSymbolAddress((void**)&w3l, w_3_lo);
    cudaGetSymbolAddress((void**)&woh, w_out_hi);  cudaGetSymbolAddress((void**)&wol, w_out_lo);
    cudaGetSymbolAddress((void**)&xw,  g_xw);
    cudaGetSymbolAddress((void**)&xw2, g_xw2);
    cudaGetSymbolAddress((void**)&z,   g_z);
    cudaGetSymbolAddress((void**)&c,   g_c);

    // ---- fork ----
    cudaEventRecord(g_sp.ev_fork, 0);
    for (int k = 0; k < NSPLIT; k++)
        cudaStreamWaitEvent(g_sp.st[k], g_sp.ev_fork, 0);

    auto pw = [](cudaStream_t s, const float* W, int K, int N, int Kpad, int Npad, int perm,
                 __half* hi, __half* lo) {
        int total = Npad * Kpad;
        prep_weight<<<(total + 255) / 256, 256, 0, s>>>(W, K, N, Kpad, total, perm, hi, lo);
    };

    // distributed weight preps (LSTM weights gate-permuted)
    pw(g_sp.st[0], enc_W, FENC, GATES, XPAD, GNPAD, 1, eWh, eWl);
    pw(g_sp.st[1], dec_W, FDEC, GATES, MPAD, GNPAD, 1, dWh, dWl);
    pw(g_sp.st[2], enc_U, UU, GATES, HPAD, GNPAD, 1, eUh, eUl);
    pw(g_sp.st[3], dec_U, UU, GATES, HPAD, GNPAD, 1, dUh, dUl);
    pw(g_sp.st[4], W1, H1, H1, H1, H1, 0, w1h, w1l);
    pw(g_sp.st[5], W2, H1, H1, H1, H1, 0, w2h, w2l);
    pw(g_sp.st[6], W3, H1, H1, H1, H1, 0, w3h, w3l);
    pw(g_sp.st[7], W_map, TS*UU, H1, DPAD, H1, 0, wmh, wml);
    pw(g_sp.st[4], W_out, H1, OUTN, H1, ONPAD, 0, woh, wol);

    // all-to-all barrier on weight preps
    for (int k = 0; k < NSPLIT; k++)
        cudaEventRecord(g_sp.ev_p[k], g_sp.st[k]);
    for (int k = 0; k < NSPLIT; k++)
        for (int j = 0; j < NSPLIT; j++)
            if (j != k) cudaStreamWaitEvent(g_sp.st[k], g_sp.ev_p[j], 0);

    const int gate_grid = (HB * (UU / 2) + 255) / 256;

    for (int k = 0; k < NSPLIT; k++) {
        cudaStream_t s = g_sp.st[k];
        const __half* xa_k = xa + (size_t)k * BTH * XPAD;
        const __half* ma_k = ma + (size_t)k * BTH * MPAD;
        float*  xw_k  = xw  + (size_t)k * BTH * GATES;
        float*  xw2_k = xw2 + (size_t)k * BTH * GATES;
        float*  z_k  = z  + (size_t)k * HB * GATES;
        float*  c_k  = c  + (size_t)k * HB * UU;
        __half* h_k  = h  + (size_t)k * HB * HPAD;
        __half* d_k  = d  + (size_t)k * HB * DPAD;
        __half* t1_k = t1 + (size_t)k * HB * H1;
        __half* t2_k = t2 + (size_t)k * HB * H1;
        float*  out_k = out + (size_t)k * HB * OUTN;

        // slice-local prep
        cudaMemsetAsync(c_k, 0, (size_t)HB * UU * sizeof(float), s);
        cudaMemsetAsync(h_k, 0, (size_t)HB * HPAD * sizeof(__half), s);
        cudaMemsetAsync(d_k, 0, (size_t)HB * DPAD * sizeof(__half), s);
        {
            int tot = BTH * XPAD;
            prep_act<<<(tot + 255) / 256, 256, 0, s>>>(
                x + (size_t)k * BTH * FENC, tot, FENC, XPAD, (__half*)xa_k);
            tot = BTH * MPAD;
            prep_act<<<(tot + 255) / 256, 256, 0, s>>>(
                m + (size_t)k * BTH * FDEC, tot, FDEC, MPAD, (__half*)ma_k);
        }

        // input projections (single-pass weights, permuted bias)
        launch_mma<0, true, false, true, false, false, true>(s, BTH, GATES, XPAD, 0,
            xa_k, eWh, eWl, enc_b, nullptr, 0, xw_k, GATES, nullptr, 0);
        launch_mma<0, true, false, true, false, false, true>(s, BTH, GATES, MPAD, 0,
            ma_k, dWh, dWl, dec_b, nullptr, 0, xw2_k, GATES, nullptr, 0);

        // encoder recurrence (hi everywhere + lo on g-gate block)
        for (int t = 0; t < TS; t++) {
            launch_mma<0, false, true, true, false, true>(s, HB, GATES, HPAD, NLO,
                h_k, eUh, eUl, nullptr, xw_k + (size_t)t * GATES, TS * GATES,
                z_k, GATES, nullptr, 0);
            lstm_gates<<<gate_grid, 256, 0, s>>>(HB, z_k, c_k, h_k, nullptr, 0);
        }

        // decoder recurrence
        for (int t = 0; t < TS; t++) {
            launch_mma<0, false, true, true, false, true>(s, HB, GATES, HPAD, NLO,
                h_k, dUh, dUl, nullptr, xw2_k + (size_t)t * GATES, TS * GATES,
                z_k, GATES, nullptr, 0);
            lstm_gates<<<gate_grid, 256, 0, s>>>(HB, z_k, c_k, h_k, d_k, t);
        }

        // MLP head (single-pass weights)
        launch_mma<1, true, false, false, true, false>(s, HB, H1, DPAD, 0, d_k, wmh, wml,
                                                       b_map, nullptr, 0, nullptr, 0, t1_k, H1);
        launch_mma<2, true, false, false, true, false>(s, HB, H1, H1, 0, t1_k, w1h, w1l,
                                                       b1, nullptr, 0, nullptr, 0, t2_k, H1);
        launch_mma<2, true, false, false, true, false>(s, HB, H1, H1, 0, t2_k, w2h, w2l,
                                                       b2, nullptr, 0, nullptr, 0, t1_k, H1);
        launch_mma<2, true, false, false, true, false>(s, HB, H1, H1, 0, t1_k, w3h, w3l,
                                                       b3, nullptr, 0, nullptr, 0, t2_k, H1);
        launch_mma<0, true, false, true, false, false>(s, HB, OUTN, H1, 0, t2_k, woh, wol,
                                                       b_out, nullptr, 0, out_k, OUTN, nullptr, 0);
    }

    // ---- join ----
    for (int k = 0; k < NSPLIT; k++) {
        cudaEventRecord(g_sp.ev_join, g_sp.st[k]);
        cudaStreamWaitEvent(0, g_sp.ev_join, 0);
    }
}